// round 4
// baseline (speedup 1.0000x reference)
#include <cuda_runtime.h>
#include <cuda_bf16.h>

// ---------------- problem constants ----------------
#define N_NODES_MAX 50000
#define N_EDGES_MAX 800000
#define N_GRAPHS_MAX 1000
#define HID 128
#define HIDH 64
#define EPS 1e-5f
#define SCAN_B 1024
#define MAX_BLOCKS ((N_NODES_MAX + SCAN_B - 1) / SCAN_B)

// ---------------- scratch (device globals, allocation-free) ----------------
__device__ __align__(16) float g_y[N_NODES_MAX * HID];      // h @ W_n
__device__ __align__(16) float g_z[N_NODES_MAX * HID];      // h @ W_r + b + agg
__device__ __align__(16) float g_h[N_NODES_MAX * HID];      // layer output
__device__ int   g_is64;                                     // index dtype flag
__device__ int   g_indeg[N_NODES_MAX];
__device__ int   g_rowexcl[N_NODES_MAX];
__device__ int   g_bsum[MAX_BLOCKS];
__device__ int   g_bsumex[MAX_BLOCKS];
__device__ int   g_row_start[N_NODES_MAX + 1];
__device__ int   g_epos[N_NODES_MAX];
__device__ int   g_esrc[N_EDGES_MAX];                        // CSR: src ids grouped by dst
__device__ int   g_gstart[N_GRAPHS_MAX + 1];
__device__ float g_stat[2 * HID];                            // col sum, col sumsq
__device__ float g_scale[HID];
__device__ float g_shift[HID];
__device__ __align__(16) float g_pooled[N_GRAPHS_MAX * HID];

// load index i from a buffer that is either int32 or int64 (flag-dispatched)
__device__ __forceinline__ int ld_idx(const void* p, long long i, int is64) {
    if (is64) return (int)((const long long*)p)[i];
    return ((const int*)p)[i];
}

// ---------------- dtype detection ----------------
// If the buffer really holds int64 indices (values < 2^31), every odd int32
// word is the zero high-half. If it holds int32 edge ids, odd words are
// random node ids and (with 2048 samples) virtually surely nonzero somewhere.
__global__ void init_flag_kernel() { g_is64 = 1; }

__global__ void detect_kernel(const void* ei, int n_i32) {
    int i = blockIdx.x * blockDim.x + threadIdx.x;
    int idx = 2 * i + 1;
    if (idx < n_i32 && ((const int*)ei)[idx] != 0) g_is64 = 0;
}

// ---------------- CSR build ----------------
__global__ void zero_indeg_kernel(int N) {
    int i = blockIdx.x * blockDim.x + threadIdx.x;
    if (i < N) g_indeg[i] = 0;
}

__global__ void count_edges_kernel(const void* __restrict__ ei, int E) {
    int e = blockIdx.x * blockDim.x + threadIdx.x;
    if (e >= E) return;
    int is64 = g_is64;
    int d = ld_idx(ei, (long long)E + e, is64);
    atomicAdd(&g_indeg[d], 1);
}

__global__ void scan1_kernel(int N) {   // blockDim = 1024
    __shared__ int sh[SCAN_B];
    int i = blockIdx.x * SCAN_B + threadIdx.x;
    int v = (i < N) ? g_indeg[i] : 0;
    sh[threadIdx.x] = v;
    __syncthreads();
    #pragma unroll
    for (int off = 1; off < SCAN_B; off <<= 1) {
        int t = 0;
        if (threadIdx.x >= off) t = sh[threadIdx.x - off];
        __syncthreads();
        sh[threadIdx.x] += t;
        __syncthreads();
    }
    if (i < N) g_rowexcl[i] = sh[threadIdx.x] - v;   // exclusive within chunk
    if (threadIdx.x == SCAN_B - 1) g_bsum[blockIdx.x] = sh[SCAN_B - 1];
}

__global__ void scan2_kernel(int nblocks) {
    if (threadIdx.x == 0) {
        int run = 0;
        for (int b = 0; b < nblocks; b++) {
            int t = g_bsum[b];
            g_bsumex[b] = run;
            run += t;
        }
    }
}

__global__ void scan3_kernel(int N, int E) {
    int i = blockIdx.x * blockDim.x + threadIdx.x;
    if (i < N) {
        int v = g_rowexcl[i] + g_bsumex[i >> 10];
        g_row_start[i] = v;
        g_epos[i] = v;
    }
    if (i == 0) g_row_start[N] = E;
}

__global__ void fill_edges_kernel(const void* __restrict__ ei, int E) {
    int e = blockIdx.x * blockDim.x + threadIdx.x;
    if (e >= E) return;
    int is64 = g_is64;
    int s = ld_idx(ei, e, is64);
    int d = ld_idx(ei, (long long)E + e, is64);
    int p = atomicAdd(&g_epos[d], 1);
    g_esrc[p] = s;
}

// batch is sorted: graph g owns rows [gstart[g], gstart[g+1])
__global__ void gstart_kernel(const void* __restrict__ batch, int N, int G) {
    int i = blockIdx.x * blockDim.x + threadIdx.x;
    if (i > N) return;
    int is64 = g_is64;
    int cur  = (i == N) ? G : ld_idx(batch, i, is64);
    int prev = (i == 0) ? -1 : ld_idx(batch, i - 1, is64);
    for (int g = prev + 1; g <= cur && g <= G; g++) g_gstart[g] = i;
}

// ---------------- dual GEMM: Y = A@Wn ; Z = A@Wr + b ----------------
#define BM 128
#define BN 128
#define BK 8
#define TM 8
#define TN 8

__global__ __launch_bounds__(256, 2)
void gemm_dual_kernel(const float* __restrict__ A_in,
                      const float* __restrict__ Wn,
                      const float* __restrict__ Wr,
                      const float* __restrict__ bias,
                      int M, int K)
{
    const float* A = A_in ? A_in : g_h;
    const float* B = (blockIdx.y == 0) ? Wn : Wr;
    float* O = (blockIdx.y == 0) ? g_y : g_z;
    const bool addb = (blockIdx.y == 1);

    __shared__ float As[BK][BM + 4];
    __shared__ float Bs[BK][BN];

    int t = threadIdx.x;            // 0..255
    int tx = t & 15;                // n-dim
    int ty = t >> 4;                // m-dim
    int row0 = blockIdx.x * BM;

    int aRow = t >> 1;
    int aCol = (t & 1) * 4;
    int bRow = t >> 5;
    int bCol = (t & 31) * 4;

    float acc[TM][TN] = {};

    for (int kt = 0; kt < K; kt += BK) {
        int r = row0 + aRow;
        #pragma unroll
        for (int i = 0; i < 4; i++) {
            int k = kt + aCol + i;
            float v = 0.f;
            if (k < K && r < M) v = A[(size_t)r * K + k];
            As[aCol + i][aRow] = v;
        }
        {
            int k = kt + bRow;
            float4 v = make_float4(0.f, 0.f, 0.f, 0.f);
            if (k < K) v = *(const float4*)&B[(size_t)k * HID + bCol];
            *(float4*)&Bs[bRow][bCol] = v;
        }
        __syncthreads();

        #pragma unroll
        for (int kk = 0; kk < BK; kk++) {
            float a[TM], b[TN];
            #pragma unroll
            for (int i = 0; i < TM; i++) a[i] = As[kk][ty * TM + i];
            #pragma unroll
            for (int j = 0; j < TN; j++) b[j] = Bs[kk][tx * TN + j];
            #pragma unroll
            for (int i = 0; i < TM; i++)
                #pragma unroll
                for (int j = 0; j < TN; j++)
                    acc[i][j] = fmaf(a[i], b[j], acc[i][j]);
        }
        __syncthreads();
    }

    #pragma unroll
    for (int i = 0; i < TM; i++) {
        int r = row0 + ty * TM + i;
        if (r >= M) continue;
        #pragma unroll
        for (int j = 0; j < TN; j += 4) {
            int c = tx * TN + j;
            float4 v = make_float4(acc[i][j], acc[i][j+1], acc[i][j+2], acc[i][j+3]);
            if (addb) {
                v.x += bias[c]; v.y += bias[c+1]; v.z += bias[c+2]; v.w += bias[c+3];
            }
            *(float4*)&O[(size_t)r * HID + c] = v;
        }
    }
}

// ---------------- gather-mean: Z[d] += mean_{s in N(d)} Y[s] ----------------
// one warp per dst node; lane handles channels [4*lane, 4*lane+4)
__global__ void aggregate_kernel(int N) {
    int d = blockIdx.x * 8 + (threadIdx.x >> 5);
    int lane = threadIdx.x & 31;
    if (d >= N) return;
    int s0 = g_row_start[d];
    int s1 = g_row_start[d + 1];
    int deg = s1 - s0;
    float inv = 1.0f / (float)(deg > 1 ? deg : 1);

    float4 acc = make_float4(0.f, 0.f, 0.f, 0.f);
    int j = s0;
    for (; j + 1 < s1; j += 2) {
        int sa = g_esrc[j];
        int sb = g_esrc[j + 1];
        float4 va = ((const float4*)g_y)[(size_t)sa * 32 + lane];
        float4 vb = ((const float4*)g_y)[(size_t)sb * 32 + lane];
        acc.x += va.x + vb.x; acc.y += va.y + vb.y;
        acc.z += va.z + vb.z; acc.w += va.w + vb.w;
    }
    if (j < s1) {
        int sa = g_esrc[j];
        float4 va = ((const float4*)g_y)[(size_t)sa * 32 + lane];
        acc.x += va.x; acc.y += va.y; acc.z += va.z; acc.w += va.w;
    }

    float4 z = ((const float4*)g_z)[(size_t)d * 32 + lane];
    z.x = fmaf(acc.x, inv, z.x);
    z.y = fmaf(acc.y, inv, z.y);
    z.z = fmaf(acc.z, inv, z.z);
    z.w = fmaf(acc.w, inv, z.w);
    ((float4*)g_z)[(size_t)d * 32 + lane] = z;
}

// ---------------- BatchNorm (training mode, biased var) ----------------
__global__ void zero_stats_kernel() {
    int i = threadIdx.x;
    if (i < 2 * HID) g_stat[i] = 0.f;
}

__global__ void bn_stats_kernel(int M) {
    int c = threadIdx.x;   // 0..127
    float s = 0.f, q = 0.f;
    for (int r = blockIdx.x; r < M; r += gridDim.x) {
        float v = g_z[(size_t)r * HID + c];
        s += v;
        q += v * v;
    }
    atomicAdd(&g_stat[c], s);
    atomicAdd(&g_stat[HID + c], q);
}

__global__ void bn_finalize_kernel(const float* __restrict__ gamma,
                                   const float* __restrict__ beta, int M) {
    int c = threadIdx.x;
    float inv_m = 1.0f / (float)M;
    float mu = g_stat[c] * inv_m;
    float var = fmaxf(g_stat[HID + c] * inv_m - mu * mu, 0.f);
    float sc = gamma[c] * rsqrtf(var + EPS);
    g_scale[c] = sc;
    g_shift[c] = beta[c] - mu * sc;
}

__global__ void norm_relu_kernel(int M) {
    int idx = blockIdx.x * blockDim.x + threadIdx.x;  // float4 index
    int total = M * 32;
    if (idx >= total) return;
    int c4 = idx & 31;
    float4 z = ((const float4*)g_z)[idx];
    float4 sc = ((const float4*)g_scale)[c4];
    float4 sh = ((const float4*)g_shift)[c4];
    float4 h;
    h.x = fmaxf(fmaf(z.x, sc.x, sh.x), 0.f);
    h.y = fmaxf(fmaf(z.y, sc.y, sh.y), 0.f);
    h.z = fmaxf(fmaf(z.z, sc.z, sh.z), 0.f);
    h.w = fmaxf(fmaf(z.w, sc.w, sh.w), 0.f);
    ((float4*)g_h)[idx] = h;
}

// ---------------- global mean pool (segmented, batch sorted) ----------------
__global__ void pool_kernel(int G) {
    int g = blockIdx.x;
    int c = threadIdx.x;   // 0..127
    if (g >= G) return;
    int r0 = g_gstart[g];
    int r1 = g_gstart[g + 1];
    float s = 0.f;
    for (int r = r0; r < r1; r++) s += g_h[(size_t)r * HID + c];
    int cnt = r1 - r0;
    g_pooled[(size_t)g * HID + c] = s / (float)(cnt > 1 ? cnt : 1);
}

// ---------------- MLP head: relu(pooled@Wh1+bh1)@Wh2+bh2 ----------------
__global__ void head_kernel(const float* __restrict__ Wh1,
                            const float* __restrict__ bh1,
                            const float* __restrict__ Wh2,
                            const float* __restrict__ bh2,
                            float* __restrict__ out, int G)
{
    int g = blockIdx.x;
    int t = threadIdx.x;   // 0..63
    if (g >= G) return;
    float acc = bh1[t];
    #pragma unroll 8
    for (int k = 0; k < HID; k++)
        acc = fmaf(g_pooled[(size_t)g * HID + k], Wh1[k * HIDH + t], acc);
    float v = fmaxf(acc, 0.f) * Wh2[t];
    #pragma unroll
    for (int off = 16; off; off >>= 1)
        v += __shfl_down_sync(0xffffffff, v, off);
    __shared__ float sred[2];
    if ((t & 31) == 0) sred[t >> 5] = v;
    __syncthreads();
    if (t == 0) out[g] = sred[0] + sred[1] + bh2[0];
}

// ---------------- launch ----------------
extern "C" void kernel_launch(void* const* d_in, const int* in_sizes, int n_in,
                              void* d_out, int out_size) {
    const float* x     = (const float*)d_in[0];
    const void*  ei    = d_in[1];
    const void*  batch = d_in[2];

    const float* W_n0 = (const float*)d_in[3];
    const float* b0   = (const float*)d_in[4];
    const float* W_r0 = (const float*)d_in[5];
    const float* g0   = (const float*)d_in[6];
    const float* be0  = (const float*)d_in[7];

    const float* W_n1 = (const float*)d_in[8];
    const float* b1   = (const float*)d_in[9];
    const float* W_r1 = (const float*)d_in[10];
    const float* g1   = (const float*)d_in[11];
    const float* be1  = (const float*)d_in[12];

    const float* W_n2 = (const float*)d_in[13];
    const float* b2   = (const float*)d_in[14];
    const float* W_r2 = (const float*)d_in[15];
    const float* g2   = (const float*)d_in[16];
    const float* be2  = (const float*)d_in[17];

    const float* Wh1 = (const float*)d_in[18];
    const float* bh1 = (const float*)d_in[19];
    const float* Wh2 = (const float*)d_in[20];
    const float* bh2 = (const float*)d_in[21];

    float* out = (float*)d_out;

    const int N = in_sizes[2];            // 50000 nodes
    const int E = in_sizes[1] / 2;        // 800000 edges
    const int G = out_size;               // 1000 graphs
    const int IN_CH = in_sizes[0] / N;    // 78

    // ---- index dtype detection (device-side, capture-safe) ----
    init_flag_kernel<<<1, 1>>>();
    detect_kernel<<<8, 256>>>(ei, in_sizes[1]);   // samples first 4096 int32 words

    // ---- CSR + segment prep ----
    int nscan = (N + SCAN_B - 1) / SCAN_B;
    zero_indeg_kernel<<<(N + 255) / 256, 256>>>(N);
    count_edges_kernel<<<(E + 255) / 256, 256>>>(ei, E);
    scan1_kernel<<<nscan, SCAN_B>>>(N);
    scan2_kernel<<<1, 32>>>(nscan);
    scan3_kernel<<<(N + 255) / 256, 256>>>(N, E);
    fill_edges_kernel<<<(E + 255) / 256, 256>>>(ei, E);
    gstart_kernel<<<(N + 256) / 256, 256>>>(batch, N, G);

    dim3 gemm_grid((N + BM - 1) / BM, 2);
    int agg_blocks  = (N + 7) / 8;
    int norm_blocks = (N * 32 + 255) / 256;

    const float* Wn[3] = {W_n0, W_n1, W_n2};
    const float* Wr[3] = {W_r0, W_r1, W_r2};
    const float* bb[3] = {b0, b1, b2};
    const float* gg[3] = {g0, g1, g2};
    const float* be[3] = {be0, be1, be2};

    for (int l = 0; l < 3; l++) {
        const float* A = (l == 0) ? x : nullptr;   // nullptr -> g_h inside kernel
        int K = (l == 0) ? IN_CH : HID;
        gemm_dual_kernel<<<gemm_grid, 256>>>(A, Wn[l], Wr[l], bb[l], N, K);
        aggregate_kernel<<<agg_blocks, 256>>>(N);
        zero_stats_kernel<<<1, 256>>>();
        bn_stats_kernel<<<1024, HID>>>(N);
        bn_finalize_kernel<<<1, HID>>>(gg[l], be[l], N);
        norm_relu_kernel<<<norm_blocks, 256>>>(N);
    }

    pool_kernel<<<G, HID>>>(G);
    head_kernel<<<G, HIDH>>>(Wh1, bh1, Wh2, bh2, out, G);
}

// round 6
// speedup vs baseline: 1.1158x; 1.1158x over previous
#include <cuda_runtime.h>
#include <cuda_bf16.h>
#include <cstdint>

// ---------------- problem constants ----------------
#define N_NODES_MAX 50000
#define N_EDGES_MAX 800000
#define N_GRAPHS_MAX 1000
#define HID 128
#define HIDH 64
#define KPAD 128
#define EPS 1e-5f
#define SCAN_B 1024
#define MAX_BLOCKS ((N_NODES_MAX + SCAN_B - 1) / SCAN_B)

// ---------------- scratch (device globals, allocation-free) ----------------
__device__ __align__(16) float g_y[N_NODES_MAX * HID];      // h @ W_n
__device__ __align__(16) float g_z[N_NODES_MAX * HID];      // h @ W_r + b + agg
__device__ __align__(16) float g_h[N_NODES_MAX * HID];      // layer output (fp32)
__device__ __align__(16) __nv_bfloat16 g_ax_hi[N_NODES_MAX * KPAD];  // layer-0 input hi
__device__ __align__(16) __nv_bfloat16 g_ax_lo[N_NODES_MAX * KPAD];  // layer-0 input lo
__device__ __align__(16) __nv_bfloat16 g_ah_hi[N_NODES_MAX * KPAD];  // layer 1/2 input hi
__device__ __align__(16) __nv_bfloat16 g_ah_lo[N_NODES_MAX * KPAD];  // layer 1/2 input lo
__device__ __align__(16) __nv_bfloat16 g_bw_hi[3][256 * KPAD];       // [Wn|Wr]^T hi, [n][k]
__device__ __align__(16) __nv_bfloat16 g_bw_lo[3][256 * KPAD];       // [Wn|Wr]^T lo
__device__ int   g_is64;
__device__ int   g_indeg[N_NODES_MAX];
__device__ int   g_rowexcl[N_NODES_MAX];
__device__ int   g_bsum[MAX_BLOCKS];
__device__ int   g_bsumex[MAX_BLOCKS];
__device__ int   g_row_start[N_NODES_MAX + 1];
__device__ int   g_epos[N_NODES_MAX];
__device__ int   g_esrc[N_EDGES_MAX];
__device__ int   g_gstart[N_GRAPHS_MAX + 1];
__device__ float g_stat[2 * HID];
__device__ float g_scale[HID];
__device__ float g_shift[HID];
__device__ __align__(16) float g_pooled[N_GRAPHS_MAX * HID];

// ---------------- index-width handling ----------------
__device__ __forceinline__ int ld_idx(const void* p, long long i, int is64) {
    if (is64) return (int)((const long long*)p)[i];
    return ((const int*)p)[i];
}

__global__ void init_flag_kernel() { g_is64 = 1; }

__global__ void detect_kernel(const void* ei, int n_i32) {
    int i = blockIdx.x * blockDim.x + threadIdx.x;
    int idx = 2 * i + 1;
    if (idx < n_i32 && ((const int*)ei)[idx] != 0) g_is64 = 0;
}

// ---------------- CSR build ----------------
__global__ void zero_indeg_kernel(int N) {
    int i = blockIdx.x * blockDim.x + threadIdx.x;
    if (i < N) g_indeg[i] = 0;
}

__global__ void count_edges_kernel(const void* __restrict__ ei, int E) {
    int e = blockIdx.x * blockDim.x + threadIdx.x;
    if (e >= E) return;
    atomicAdd(&g_indeg[ld_idx(ei, (long long)E + e, g_is64)], 1);
}

__global__ void scan1_kernel(int N) {
    __shared__ int sh[SCAN_B];
    int i = blockIdx.x * SCAN_B + threadIdx.x;
    int v = (i < N) ? g_indeg[i] : 0;
    sh[threadIdx.x] = v;
    __syncthreads();
    #pragma unroll
    for (int off = 1; off < SCAN_B; off <<= 1) {
        int t = 0;
        if (threadIdx.x >= off) t = sh[threadIdx.x - off];
        __syncthreads();
        sh[threadIdx.x] += t;
        __syncthreads();
    }
    if (i < N) g_rowexcl[i] = sh[threadIdx.x] - v;
    if (threadIdx.x == SCAN_B - 1) g_bsum[blockIdx.x] = sh[SCAN_B - 1];
}

__global__ void scan2_kernel(int nblocks) {
    if (threadIdx.x == 0) {
        int run = 0;
        for (int b = 0; b < nblocks; b++) { int t = g_bsum[b]; g_bsumex[b] = run; run += t; }
    }
}

__global__ void scan3_kernel(int N, int E) {
    int i = blockIdx.x * blockDim.x + threadIdx.x;
    if (i < N) {
        int v = g_rowexcl[i] + g_bsumex[i >> 10];
        g_row_start[i] = v;
        g_epos[i] = v;
    }
    if (i == 0) g_row_start[N] = E;
}

__global__ void fill_edges_kernel(const void* __restrict__ ei, int E) {
    int e = blockIdx.x * blockDim.x + threadIdx.x;
    if (e >= E) return;
    int is64 = g_is64;
    int s = ld_idx(ei, e, is64);
    int d = ld_idx(ei, (long long)E + e, is64);
    g_esrc[atomicAdd(&g_epos[d], 1)] = s;
}

__global__ void gstart_kernel(const void* __restrict__ batch, int N, int G) {
    int i = blockIdx.x * blockDim.x + threadIdx.x;
    if (i > N) return;
    int is64 = g_is64;
    int cur  = (i == N) ? G : ld_idx(batch, i, is64);
    int prev = (i == 0) ? -1 : ld_idx(batch, i - 1, is64);
    for (int g = prev + 1; g <= cur && g <= G; g++) g_gstart[g] = i;
}

// ---------------- bf16 split conversions ----------------
__global__ void convert_x_kernel(const float* __restrict__ x, int N, int IN_CH) {
    int idx = blockIdx.x * blockDim.x + threadIdx.x;
    if (idx >= N * KPAD) return;
    int r = idx >> 7, k = idx & 127;
    float v = (k < IN_CH) ? x[(size_t)r * IN_CH + k] : 0.f;
    __nv_bfloat16 hi = __float2bfloat16(v);
    g_ax_hi[idx] = hi;
    g_ax_lo[idx] = __float2bfloat16(v - __bfloat162float(hi));
}

// B[n][k] = Wcat[k][n]  (n<128 -> Wn, else Wr), zero-padded k >= K_real
__global__ void prep_weights_kernel(const float* __restrict__ Wn,
                                    const float* __restrict__ Wr,
                                    int layer, int K_real) {
    int idx = blockIdx.x * blockDim.x + threadIdx.x;
    if (idx >= 256 * KPAD) return;
    int n = idx >> 7, k = idx & 127;
    float v = 0.f;
    if (k < K_real) v = (n < HID) ? Wn[(size_t)k * HID + n] : Wr[(size_t)k * HID + (n - HID)];
    __nv_bfloat16 hi = __float2bfloat16(v);
    g_bw_hi[layer][idx] = hi;
    g_bw_lo[layer][idx] = __float2bfloat16(v - __bfloat162float(hi));
}

// ---------------- mma.sync dual GEMM --------------------------------------
// [Y|Z](M x 256) = A(M x 128) @ Bcat^T, split precision in 3 passes:
//   D = Ahi*Bhi + Ahi*Blo + Alo*Bhi  (fp32 accum; lo*lo dropped, ~1e-5)
// CTA: 128 rows x 128 cols. blockIdx.y: 0 -> g_y (B rows 0..127),
//                                       1 -> g_z + bias (B rows 128..255).
// 8 warps as 4(M) x 2(N); warp tile 32x64; mma.m16n8k16.bf16.
__device__ __forceinline__ void mma16816(float* c, const uint32_t* a, const uint32_t* b) {
    asm volatile(
        "mma.sync.aligned.m16n8k16.row.col.f32.bf16.bf16.f32 "
        "{%0,%1,%2,%3}, {%4,%5,%6,%7}, {%8,%9}, {%0,%1,%2,%3};"
        : "+f"(c[0]), "+f"(c[1]), "+f"(c[2]), "+f"(c[3])
        : "r"(a[0]), "r"(a[1]), "r"(a[2]), "r"(a[3]), "r"(b[0]), "r"(b[1]));
}

__global__ __launch_bounds__(256)
void gemm_mma_kernel(const uint4* __restrict__ a_hi, const uint4* __restrict__ a_lo,
                     const uint4* __restrict__ b_hi, const uint4* __restrict__ b_lo,
                     const float* __restrict__ bias, int M)
{
    __shared__ uint32_t sA[128][9];   // 16 bf16 per row (8 u32), pad to 9
    __shared__ uint32_t sB[128][9];

    int tid = threadIdx.x;
    int lane = tid & 31;
    int wid = tid >> 5;
    int wm = wid & 3;          // warp M index (0..3)
    int wn = wid >> 2;         // warp N index (0..1)
    int row0 = blockIdx.x * 128;
    int half = blockIdx.y;     // 0: Y, 1: Z
    int brow0 = half * 128;    // B rows for this half

    // load mapping: thread -> (row = tid/2, 8-bf16 half h = tid&1)
    int lr = tid >> 1;
    int lh = tid & 1;

    float acc[2][8][4];
    #pragma unroll
    for (int mi = 0; mi < 2; mi++)
        #pragma unroll
        for (int ni = 0; ni < 8; ni++)
            #pragma unroll
            for (int q = 0; q < 4; q++) acc[mi][ni][q] = 0.f;

    // 24 macro steps: pass p = s>>3 in {0,1,2}, k0 = (s&7)*16
    for (int s = 0; s < 24; s++) {
        int p = s >> 3;
        int kc = (s & 7) * 2 + lh;   // uint4 index within 16-uint4 row
        const uint4* asrc = (p < 2) ? a_hi : a_lo;
        const uint4* bsrc = (p == 1) ? b_lo : b_hi;

        // A: rows row0..row0+127, k chunk
        uint4 va = make_uint4(0, 0, 0, 0);
        if (row0 + lr < M) va = asrc[(size_t)(row0 + lr) * 16 + kc];
        sA[lr][lh * 4 + 0] = va.x;
        sA[lr][lh * 4 + 1] = va.y;
        sA[lr][lh * 4 + 2] = va.z;
        sA[lr][lh * 4 + 3] = va.w;
        // B: rows brow0..brow0+127
        uint4 vb = bsrc[(size_t)(brow0 + lr) * 16 + kc];
        sB[lr][lh * 4 + 0] = vb.x;
        sB[lr][lh * 4 + 1] = vb.y;
        sB[lr][lh * 4 + 2] = vb.z;
        sB[lr][lh * 4 + 3] = vb.w;
        __syncthreads();

        // fragments
        uint32_t afr[2][4];
        int q = lane & 3;
        int rbase = wm * 32 + (lane >> 2);
        #pragma unroll
        for (int mi = 0; mi < 2; mi++) {
            int r = rbase + mi * 16;
            afr[mi][0] = sA[r][q];
            afr[mi][1] = sA[r + 8][q];
            afr[mi][2] = sA[r][q + 4];
            afr[mi][3] = sA[r + 8][q + 4];
        }
        #pragma unroll
        for (int ni = 0; ni < 8; ni++) {
            int n = wn * 64 + ni * 8 + (lane >> 2);
            uint32_t bfr[2];
            bfr[0] = sB[n][q];
            bfr[1] = sB[n][q + 4];
            mma16816(acc[0][ni], afr[0], bfr);
            mma16816(acc[1][ni], afr[1], bfr);
        }
        __syncthreads();
    }

    // ---- epilogue ----
    float* O = half ? g_z : g_y;
    #pragma unroll
    for (int mi = 0; mi < 2; mi++) {
        int r0 = row0 + wm * 32 + mi * 16 + (lane >> 2);
        #pragma unroll
        for (int ni = 0; ni < 8; ni++) {
            int c = wn * 64 + ni * 8 + (lane & 3) * 2;
            float bx = 0.f, by = 0.f;
            if (half) { bx = bias[c]; by = bias[c + 1]; }
            if (r0 < M) {
                float2 v = make_float2(acc[mi][ni][0] + bx, acc[mi][ni][1] + by);
                *(float2*)&O[(size_t)r0 * HID + c] = v;
            }
            if (r0 + 8 < M) {
                float2 v = make_float2(acc[mi][ni][2] + bx, acc[mi][ni][3] + by);
                *(float2*)&O[(size_t)(r0 + 8) * HID + c] = v;
            }
        }
    }
}

// ---------------- gather-mean: Z[d] += mean_{s in N(d)} Y[s] ----------------
__global__ void aggregate_kernel(int N) {
    int d = blockIdx.x * 8 + (threadIdx.x >> 5);
    int lane = threadIdx.x & 31;
    if (d >= N) return;
    int s0 = g_row_start[d];
    int s1 = g_row_start[d + 1];
    int deg = s1 - s0;
    float inv = 1.0f / (float)(deg > 1 ? deg : 1);

    float4 acc = make_float4(0.f, 0.f, 0.f, 0.f);
    int j = s0;
    for (; j + 1 < s1; j += 2) {
        int sa = g_esrc[j];
        int sb = g_esrc[j + 1];
        float4 va = ((const float4*)g_y)[(size_t)sa * 32 + lane];
        float4 vb = ((const float4*)g_y)[(size_t)sb * 32 + lane];
        acc.x += va.x + vb.x; acc.y += va.y + vb.y;
        acc.z += va.z + vb.z; acc.w += va.w + vb.w;
    }
    if (j < s1) {
        int sa = g_esrc[j];
        float4 va = ((const float4*)g_y)[(size_t)sa * 32 + lane];
        acc.x += va.x; acc.y += va.y; acc.z += va.z; acc.w += va.w;
    }

    float4 z = ((const float4*)g_z)[(size_t)d * 32 + lane];
    z.x = fmaf(acc.x, inv, z.x);
    z.y = fmaf(acc.y, inv, z.y);
    z.z = fmaf(acc.z, inv, z.z);
    z.w = fmaf(acc.w, inv, z.w);
    ((float4*)g_z)[(size_t)d * 32 + lane] = z;
}

// ---------------- BatchNorm (training mode, biased var) ----------------
__global__ void zero_stats_kernel() {
    int i = threadIdx.x;
    if (i < 2 * HID) g_stat[i] = 0.f;
}

__global__ void bn_stats_kernel(int M) {
    int c = threadIdx.x;
    float s = 0.f, q = 0.f;
    for (int r = blockIdx.x; r < M; r += gridDim.x) {
        float v = g_z[(size_t)r * HID + c];
        s += v;
        q += v * v;
    }
    atomicAdd(&g_stat[c], s);
    atomicAdd(&g_stat[HID + c], q);
}

__global__ void bn_finalize_kernel(const float* __restrict__ gamma,
                                   const float* __restrict__ beta, int M) {
    int c = threadIdx.x;
    float inv_m = 1.0f / (float)M;
    float mu = g_stat[c] * inv_m;
    float var = fmaxf(g_stat[HID + c] * inv_m - mu * mu, 0.f);
    float sc = gamma[c] * rsqrtf(var + EPS);
    g_scale[c] = sc;
    g_shift[c] = beta[c] - mu * sc;
}

// fused: h = relu(z*scale+shift); also emit bf16 hi/lo split for next layer's MMA
__global__ void norm_relu_kernel(int M) {
    int idx = blockIdx.x * blockDim.x + threadIdx.x;  // float4 index
    int total = M * 32;
    if (idx >= total) return;
    int c4 = idx & 31;
    float4 z = ((const float4*)g_z)[idx];
    float4 sc = ((const float4*)g_scale)[c4];
    float4 sh = ((const float4*)g_shift)[c4];
    float4 h;
    h.x = fmaxf(fmaf(z.x, sc.x, sh.x), 0.f);
    h.y = fmaxf(fmaf(z.y, sc.y, sh.y), 0.f);
    h.z = fmaxf(fmaf(z.z, sc.z, sh.z), 0.f);
    h.w = fmaxf(fmaf(z.w, sc.w, sh.w), 0.f);
    ((float4*)g_h)[idx] = h;

    __nv_bfloat16 hx = __float2bfloat16(h.x);
    __nv_bfloat16 hy = __float2bfloat16(h.y);
    __nv_bfloat16 hz = __float2bfloat16(h.z);
    __nv_bfloat16 hw = __float2bfloat16(h.w);
    __nv_bfloat162* phi = (__nv_bfloat162*)&g_ah_hi[(size_t)idx * 4];
    phi[0] = __nv_bfloat162(hx, hy);
    phi[1] = __nv_bfloat162(hz, hw);
    __nv_bfloat162* plo = (__nv_bfloat162*)&g_ah_lo[(size_t)idx * 4];
    plo[0] = __nv_bfloat162(__float2bfloat16(h.x - __bfloat162float(hx)),
                            __float2bfloat16(h.y - __bfloat162float(hy)));
    plo[1] = __nv_bfloat162(__float2bfloat16(h.z - __bfloat162float(hz)),
                            __float2bfloat16(h.w - __bfloat162float(hw)));
}

// ---------------- global mean pool (segmented, batch sorted) ----------------
__global__ void pool_kernel(int G) {
    int g = blockIdx.x;
    int c = threadIdx.x;
    if (g >= G) return;
    int r0 = g_gstart[g];
    int r1 = g_gstart[g + 1];
    float s = 0.f;
    for (int r = r0; r < r1; r++) s += g_h[(size_t)r * HID + c];
    int cnt = r1 - r0;
    g_pooled[(size_t)g * HID + c] = s / (float)(cnt > 1 ? cnt : 1);
}

// ---------------- MLP head ----------------
__global__ void head_kernel(const float* __restrict__ Wh1,
                            const float* __restrict__ bh1,
                            const float* __restrict__ Wh2,
                            const float* __restrict__ bh2,
                            float* __restrict__ out, int G)
{
    int g = blockIdx.x;
    int t = threadIdx.x;
    if (g >= G) return;
    float acc = bh1[t];
    #pragma unroll 8
    for (int k = 0; k < HID; k++)
        acc = fmaf(g_pooled[(size_t)g * HID + k], Wh1[k * HIDH + t], acc);
    float v = fmaxf(acc, 0.f) * Wh2[t];
    #pragma unroll
    for (int off = 16; off; off >>= 1)
        v += __shfl_down_sync(0xffffffff, v, off);
    __shared__ float sred[2];
    if ((t & 31) == 0) sred[t >> 5] = v;
    __syncthreads();
    if (t == 0) out[g] = sred[0] + sred[1] + bh2[0];
}

// ---------------- launch ----------------
extern "C" void kernel_launch(void* const* d_in, const int* in_sizes, int n_in,
                              void* d_out, int out_size) {
    const float* x     = (const float*)d_in[0];
    const void*  ei    = d_in[1];
    const void*  batch = d_in[2];

    const float* W_n0 = (const float*)d_in[3];
    const float* b0   = (const float*)d_in[4];
    const float* W_r0 = (const float*)d_in[5];
    const float* g0   = (const float*)d_in[6];
    const float* be0  = (const float*)d_in[7];

    const float* W_n1 = (const float*)d_in[8];
    const float* b1   = (const float*)d_in[9];
    const float* W_r1 = (const float*)d_in[10];
    const float* g1   = (const float*)d_in[11];
    const float* be1  = (const float*)d_in[12];

    const float* W_n2 = (const float*)d_in[13];
    const float* b2   = (const float*)d_in[14];
    const float* W_r2 = (const float*)d_in[15];
    const float* g2   = (const float*)d_in[16];
    const float* be2  = (const float*)d_in[17];

    const float* Wh1 = (const float*)d_in[18];
    const float* bh1 = (const float*)d_in[19];
    const float* Wh2 = (const float*)d_in[20];
    const float* bh2 = (const float*)d_in[21];

    float* out = (float*)d_out;

    const int N = in_sizes[2];
    const int E = in_sizes[1] / 2;
    const int G = out_size;
    const int IN_CH = in_sizes[0] / N;

    // ---- index dtype detection + CSR/segment prep ----
    init_flag_kernel<<<1, 1>>>();
    detect_kernel<<<8, 256>>>(ei, in_sizes[1]);
    int nscan = (N + SCAN_B - 1) / SCAN_B;
    zero_indeg_kernel<<<(N + 255) / 256, 256>>>(N);
    count_edges_kernel<<<(E + 255) / 256, 256>>>(ei, E);
    scan1_kernel<<<nscan, SCAN_B>>>(N);
    scan2_kernel<<<1, 32>>>(nscan);
    scan3_kernel<<<(N + 255) / 256, 256>>>(N, E);
    fill_edges_kernel<<<(E + 255) / 256, 256>>>(ei, E);
    gstart_kernel<<<(N + 256) / 256, 256>>>(batch, N, G);

    // ---- bf16 split preprocessing ----
    convert_x_kernel<<<(N * KPAD + 255) / 256, 256>>>(x, N, IN_CH);
    prep_weights_kernel<<<(256 * KPAD + 255) / 256, 256>>>(W_n0, W_r0, 0, IN_CH);
    prep_weights_kernel<<<(256 * KPAD + 255) / 256, 256>>>(W_n1, W_r1, 1, HID);
    prep_weights_kernel<<<(256 * KPAD + 255) / 256, 256>>>(W_n2, W_r2, 2, HID);

    dim3 gemm_grid((N + 127) / 128, 2);
    int agg_blocks  = (N + 7) / 8;
    int norm_blocks = (N * 32 + 255) / 256;

    const float* bb[3] = {b0, b1, b2};
    const float* gg[3] = {g0, g1, g2};
    const float* be[3] = {be0, be1, be2};

    // device pointers to scratch (host-side symbol offsets are linker constants)
    // note: we pass the A/B arrays via their __device__ symbols directly in kernel args
    for (int l = 0; l < 3; l++) {
        const uint4* ahi;
        const uint4* alo;
        const uint4* bhi;
        const uint4* blo;
        // obtain device addresses of __device__ globals via kernel-visible names:
        // (cudaGetSymbolAddress is host API but NOT a stream op; safe pre-capture? To be
        //  fully capture-safe we compute them once per call; it performs no stream work.)
        void* p;
        cudaGetSymbolAddress(&p, (l == 0) ? g_ax_hi : g_ah_hi); ahi = (const uint4*)p;
        cudaGetSymbolAddress(&p, (l == 0) ? g_ax_lo : g_ah_lo); alo = (const uint4*)p;
        cudaGetSymbolAddress(&p, g_bw_hi); bhi = (const uint4*)p + (size_t)l * (256 * KPAD / 8);
        cudaGetSymbolAddress(&p, g_bw_lo); blo = (const uint4*)p + (size_t)l * (256 * KPAD / 8);

        gemm_mma_kernel<<<gemm_grid, 256>>>(ahi, alo, bhi, blo, bb[l], N);
        aggregate_kernel<<<agg_blocks, 256>>>(N);
        zero_stats_kernel<<<1, 256>>>();
        bn_stats_kernel<<<1024, HID>>>(N);
        bn_finalize_kernel<<<1, HID>>>(gg[l], be[l], N);
        norm_relu_kernel<<<norm_blocks, 256>>>(N);
    }

    pool_kernel<<<G, HID>>>(G);
    head_kernel<<<G, HIDH>>>(Wh1, bh1, Wh2, bh2, out, G);
}

// round 7
// speedup vs baseline: 1.4212x; 1.2737x over previous
#include <cuda_runtime.h>
#include <cuda_bf16.h>
#include <cstdint>

// ---------------- problem constants ----------------
#define N_NODES_MAX 50000
#define N_EDGES_MAX 800000
#define N_GRAPHS_MAX 1000
#define HID 128
#define HIDH 64
#define KPAD 128
#define EPS 1e-5f
#define SCAN_B 1024
#define MAX_BLOCKS ((N_NODES_MAX + SCAN_B - 1) / SCAN_B)

// ---------------- scratch (device globals, allocation-free) ----------------
__device__ __align__(16) float g_y[N_NODES_MAX * HID];      // h @ W_n
__device__ __align__(16) float g_z[N_NODES_MAX * HID];      // h @ W_r + b + agg
__device__ __align__(16) float g_h[N_NODES_MAX * HID];      // layer output (fp32)
__device__ __align__(16) __nv_bfloat16 g_ax_hi[N_NODES_MAX * KPAD];
__device__ __align__(16) __nv_bfloat16 g_ax_lo[N_NODES_MAX * KPAD];
__device__ __align__(16) __nv_bfloat16 g_ah_hi[N_NODES_MAX * KPAD];
__device__ __align__(16) __nv_bfloat16 g_ah_lo[N_NODES_MAX * KPAD];
__device__ __align__(16) __nv_bfloat16 g_bw_hi[3][256 * KPAD];   // [Wn|Wr]^T hi, [n][k]
__device__ __align__(16) __nv_bfloat16 g_bw_lo[3][256 * KPAD];
__device__ int   g_is64;
__device__ int   g_indeg[N_NODES_MAX];
__device__ int   g_rowexcl[N_NODES_MAX];
__device__ int   g_bsum[MAX_BLOCKS];
__device__ int   g_bsumex[MAX_BLOCKS];
__device__ int   g_row_start[N_NODES_MAX + 1];
__device__ int   g_epos[N_NODES_MAX];
__device__ int   g_esrc[N_EDGES_MAX];
__device__ int   g_gstart[N_GRAPHS_MAX + 1];
__device__ float g_stat[2 * HID];
__device__ float g_scale[HID];
__device__ float g_shift[HID];
__device__ __align__(16) float g_pooled[N_GRAPHS_MAX * HID];

// ---------------- index-width handling ----------------
__device__ __forceinline__ int ld_idx(const void* p, long long i, int is64) {
    if (is64) return (int)((const long long*)p)[i];
    return ((const int*)p)[i];
}

__global__ void init_flag_kernel() { g_is64 = 1; }

__global__ void detect_kernel(const void* ei, int n_i32) {
    int i = blockIdx.x * blockDim.x + threadIdx.x;
    int idx = 2 * i + 1;
    if (idx < n_i32 && ((const int*)ei)[idx] != 0) g_is64 = 0;
}

// ---------------- CSR build ----------------
__global__ void zero_indeg_kernel(int N) {
    int i = blockIdx.x * blockDim.x + threadIdx.x;
    if (i < N) g_indeg[i] = 0;
}

__global__ void count_edges_kernel(const void* __restrict__ ei, int E) {
    int e = blockIdx.x * blockDim.x + threadIdx.x;
    if (e >= E) return;
    atomicAdd(&g_indeg[ld_idx(ei, (long long)E + e, g_is64)], 1);
}

__global__ void scan1_kernel(int N) {
    __shared__ int sh[SCAN_B];
    int i = blockIdx.x * SCAN_B + threadIdx.x;
    int v = (i < N) ? g_indeg[i] : 0;
    sh[threadIdx.x] = v;
    __syncthreads();
    #pragma unroll
    for (int off = 1; off < SCAN_B; off <<= 1) {
        int t = 0;
        if (threadIdx.x >= off) t = sh[threadIdx.x - off];
        __syncthreads();
        sh[threadIdx.x] += t;
        __syncthreads();
    }
    if (i < N) g_rowexcl[i] = sh[threadIdx.x] - v;
    if (threadIdx.x == SCAN_B - 1) g_bsum[blockIdx.x] = sh[SCAN_B - 1];
}

__global__ void scan2_kernel(int nblocks) {
    if (threadIdx.x == 0) {
        int run = 0;
        for (int b = 0; b < nblocks; b++) { int t = g_bsum[b]; g_bsumex[b] = run; run += t; }
    }
}

__global__ void scan3_kernel(int N, int E) {
    int i = blockIdx.x * blockDim.x + threadIdx.x;
    if (i < N) {
        int v = g_rowexcl[i] + g_bsumex[i >> 10];
        g_row_start[i] = v;
        g_epos[i] = v;
    }
    if (i == 0) g_row_start[N] = E;
}

__global__ void fill_edges_kernel(const void* __restrict__ ei, int E) {
    int e = blockIdx.x * blockDim.x + threadIdx.x;
    if (e >= E) return;
    int is64 = g_is64;
    int s = ld_idx(ei, e, is64);
    int d = ld_idx(ei, (long long)E + e, is64);
    g_esrc[atomicAdd(&g_epos[d], 1)] = s;
}

__global__ void gstart_kernel(const void* __restrict__ batch, int N, int G) {
    int i = blockIdx.x * blockDim.x + threadIdx.x;
    if (i > N) return;
    int is64 = g_is64;
    int cur  = (i == N) ? G : ld_idx(batch, i, is64);
    int prev = (i == 0) ? -1 : ld_idx(batch, i - 1, is64);
    for (int g = prev + 1; g <= cur && g <= G; g++) g_gstart[g] = i;
}

// ---------------- bf16 split conversions ----------------
__global__ void convert_x_kernel(const float* __restrict__ x, int N, int IN_CH) {
    int idx = blockIdx.x * blockDim.x + threadIdx.x;
    if (idx >= N * KPAD) return;
    int r = idx >> 7, k = idx & 127;
    float v = (k < IN_CH) ? x[(size_t)r * IN_CH + k] : 0.f;
    __nv_bfloat16 hi = __float2bfloat16(v);
    g_ax_hi[idx] = hi;
    g_ax_lo[idx] = __float2bfloat16(v - __bfloat162float(hi));
}

__global__ void prep_weights_kernel(const float* __restrict__ Wn,
                                    const float* __restrict__ Wr,
                                    int layer, int K_real) {
    int idx = blockIdx.x * blockDim.x + threadIdx.x;
    if (idx >= 256 * KPAD) return;
    int n = idx >> 7, k = idx & 127;
    float v = 0.f;
    if (k < K_real) v = (n < HID) ? Wn[(size_t)k * HID + n] : Wr[(size_t)k * HID + (n - HID)];
    __nv_bfloat16 hi = __float2bfloat16(v);
    g_bw_hi[layer][idx] = hi;
    g_bw_lo[layer][idx] = __float2bfloat16(v - __bfloat162float(hi));
}

// ---------------- mma.sync dual GEMM (SMEM-resident, ldmatrix) -------------
// [Y|Z](M x 256) = A(M x 128) @ Bcat^T, 3 precision passes from SMEM:
//   D = Ahi*Bhi + Ahi*Blo + Alo*Bhi
// blockIdx.y: 0 -> g_y (B rows 0..127), 1 -> g_z + bias (B rows 128..255).
// 8 warps 4(M)x2(N), warp tile 32x64, mma.m16n8k16.bf16.
#define PITCH 272                       // bytes per SMEM row (17 x 16B, odd -> conflict-free)
#define TILE_BYTES (128 * PITCH)        // 34816
#define SM_A_HI 0
#define SM_A_LO TILE_BYTES
#define SM_B_HI (2 * TILE_BYTES)
#define SM_B_LO (3 * TILE_BYTES)
#define SM_TOTAL (4 * TILE_BYTES)       // 139264

__device__ __forceinline__ uint32_t smem_u32(const void* p) {
    uint32_t a;
    asm("{ .reg .u64 t; cvta.to.shared.u64 t, %1; cvt.u32.u64 %0, t; }" : "=r"(a) : "l"(p));
    return a;
}

__device__ __forceinline__ void ldsm_x4(uint32_t& r0, uint32_t& r1, uint32_t& r2, uint32_t& r3,
                                        uint32_t addr) {
    asm volatile("ldmatrix.sync.aligned.m8n8.x4.shared.b16 {%0,%1,%2,%3}, [%4];"
                 : "=r"(r0), "=r"(r1), "=r"(r2), "=r"(r3) : "r"(addr));
}

__device__ __forceinline__ void mma16816(float* c, const uint32_t* a, const uint32_t* b) {
    asm volatile(
        "mma.sync.aligned.m16n8k16.row.col.f32.bf16.bf16.f32 "
        "{%0,%1,%2,%3}, {%4,%5,%6,%7}, {%8,%9}, {%0,%1,%2,%3};"
        : "+f"(c[0]), "+f"(c[1]), "+f"(c[2]), "+f"(c[3])
        : "r"(a[0]), "r"(a[1]), "r"(a[2]), "r"(a[3]), "r"(b[0]), "r"(b[1]));
}

__global__ __launch_bounds__(256)
void gemm_mma_kernel(const uint4* __restrict__ a_hi, const uint4* __restrict__ a_lo,
                     const uint4* __restrict__ b_hi, const uint4* __restrict__ b_lo,
                     const float* __restrict__ bias, int M)
{
    extern __shared__ char smem[];
    uint32_t sbase = smem_u32(smem);

    int tid = threadIdx.x;
    int lane = tid & 31;
    int wid = tid >> 5;
    int wm = wid & 3;
    int wn = wid >> 2;
    int row0 = blockIdx.x * 128;
    int half = blockIdx.y;
    int brow0 = half * 128;

    // ---- load all tiles once (each tensor: 2048 uint4 = 32KB) ----
    #pragma unroll
    for (int i = tid; i < 2048; i += 256) {
        int r = i >> 4, c16 = i & 15;
        int doff = r * PITCH + c16 * 16;
        uint4 vh = make_uint4(0, 0, 0, 0), vl = make_uint4(0, 0, 0, 0);
        if (row0 + r < M) {
            vh = a_hi[(size_t)(row0 + r) * 16 + c16];
            vl = a_lo[(size_t)(row0 + r) * 16 + c16];
        }
        *(uint4*)(smem + SM_A_HI + doff) = vh;
        *(uint4*)(smem + SM_A_LO + doff) = vl;
        uint4 wh = b_hi[(size_t)(brow0 + r) * 16 + c16];
        uint4 wl = b_lo[(size_t)(brow0 + r) * 16 + c16];
        *(uint4*)(smem + SM_B_HI + doff) = wh;
        *(uint4*)(smem + SM_B_LO + doff) = wl;
    }
    __syncthreads();

    float acc[2][8][4];
    #pragma unroll
    for (int mi = 0; mi < 2; mi++)
        #pragma unroll
        for (int ni = 0; ni < 8; ni++)
            #pragma unroll
            for (int q = 0; q < 4; q++) acc[mi][ni][q] = 0.f;

    // per-lane ldmatrix base offsets (within a tile)
    // A: lanes 0-15 -> rows rbase+0..15 @k0 ; lanes 16-31 -> same rows @k+8
    uint32_t a_off[2];
    #pragma unroll
    for (int mi = 0; mi < 2; mi++)
        a_off[mi] = (uint32_t)((wm * 32 + mi * 16 + (lane & 15)) * PITCH + (lane >> 4) * 16);
    // B: groups of 8 lanes -> (rows +0/+0/+8/+8, koff 0/16/0/16)
    uint32_t b_off[4];
    {
        int grp = lane >> 3, rin = lane & 7;
        int radd = (grp >= 2) ? 8 : 0;
        int koff = (grp & 1) * 16;
        #pragma unroll
        for (int pi = 0; pi < 4; pi++)
            b_off[pi] = (uint32_t)((wn * 64 + pi * 16 + radd + rin) * PITCH + koff);
    }

    const uint32_t smA[3] = { sbase + SM_A_HI, sbase + SM_A_HI, sbase + SM_A_LO };
    const uint32_t smB[3] = { sbase + SM_B_HI, sbase + SM_B_LO, sbase + SM_B_HI };

    #pragma unroll
    for (int p = 0; p < 3; p++) {
        uint32_t abase = smA[p];
        uint32_t bbase = smB[p];
        #pragma unroll
        for (int k16 = 0; k16 < 8; k16++) {
            uint32_t kadd = k16 * 32;
            uint32_t afr[2][4];
            #pragma unroll
            for (int mi = 0; mi < 2; mi++)
                ldsm_x4(afr[mi][0], afr[mi][1], afr[mi][2], afr[mi][3],
                        abase + a_off[mi] + kadd);
            uint32_t bfr[8][2];
            #pragma unroll
            for (int pi = 0; pi < 4; pi++) {
                uint32_t r0, r1, r2, r3;
                ldsm_x4(r0, r1, r2, r3, bbase + b_off[pi] + kadd);
                bfr[pi * 2][0] = r0; bfr[pi * 2][1] = r1;
                bfr[pi * 2 + 1][0] = r2; bfr[pi * 2 + 1][1] = r3;
            }
            #pragma unroll
            for (int ni = 0; ni < 8; ni++) {
                mma16816(acc[0][ni], afr[0], bfr[ni]);
                mma16816(acc[1][ni], afr[1], bfr[ni]);
            }
        }
    }

    // ---- epilogue ----
    float* O = half ? g_z : g_y;
    #pragma unroll
    for (int mi = 0; mi < 2; mi++) {
        int r0 = row0 + wm * 32 + mi * 16 + (lane >> 2);
        #pragma unroll
        for (int ni = 0; ni < 8; ni++) {
            int c = wn * 64 + ni * 8 + (lane & 3) * 2;
            float bx = 0.f, by = 0.f;
            if (half) { bx = bias[c]; by = bias[c + 1]; }
            if (r0 < M) {
                float2 v = make_float2(acc[mi][ni][0] + bx, acc[mi][ni][1] + by);
                *(float2*)&O[(size_t)r0 * HID + c] = v;
            }
            if (r0 + 8 < M) {
                float2 v = make_float2(acc[mi][ni][2] + bx, acc[mi][ni][3] + by);
                *(float2*)&O[(size_t)(r0 + 8) * HID + c] = v;
            }
        }
    }
}

// ---------------- gather-mean: Z[d] += mean_{s in N(d)} Y[s] ----------------
__global__ void aggregate_kernel(int N) {
    int d = blockIdx.x * 8 + (threadIdx.x >> 5);
    int lane = threadIdx.x & 31;
    if (d >= N) return;
    int s0 = g_row_start[d];
    int s1 = g_row_start[d + 1];
    int deg = s1 - s0;
    float inv = 1.0f / (float)(deg > 1 ? deg : 1);

    float4 acc = make_float4(0.f, 0.f, 0.f, 0.f);
    int j = s0;
    for (; j + 1 < s1; j += 2) {
        int sa = g_esrc[j];
        int sb = g_esrc[j + 1];
        float4 va = ((const float4*)g_y)[(size_t)sa * 32 + lane];
        float4 vb = ((const float4*)g_y)[(size_t)sb * 32 + lane];
        acc.x += va.x + vb.x; acc.y += va.y + vb.y;
        acc.z += va.z + vb.z; acc.w += va.w + vb.w;
    }
    if (j < s1) {
        int sa = g_esrc[j];
        float4 va = ((const float4*)g_y)[(size_t)sa * 32 + lane];
        acc.x += va.x; acc.y += va.y; acc.z += va.z; acc.w += va.w;
    }

    float4 z = ((const float4*)g_z)[(size_t)d * 32 + lane];
    z.x = fmaf(acc.x, inv, z.x);
    z.y = fmaf(acc.y, inv, z.y);
    z.z = fmaf(acc.z, inv, z.z);
    z.w = fmaf(acc.w, inv, z.w);
    ((float4*)g_z)[(size_t)d * 32 + lane] = z;
}

// ---------------- BatchNorm (training mode, biased var) ----------------
__global__ void zero_stats_kernel() {
    int i = threadIdx.x;
    if (i < 2 * HID) g_stat[i] = 0.f;
}

__global__ void bn_stats_kernel(int M) {
    int c = threadIdx.x;
    float s = 0.f, q = 0.f;
    for (int r = blockIdx.x; r < M; r += gridDim.x) {
        float v = g_z[(size_t)r * HID + c];
        s += v;
        q += v * v;
    }
    atomicAdd(&g_stat[c], s);
    atomicAdd(&g_stat[HID + c], q);
}

__global__ void bn_finalize_kernel(const float* __restrict__ gamma,
                                   const float* __restrict__ beta, int M) {
    int c = threadIdx.x;
    float inv_m = 1.0f / (float)M;
    float mu = g_stat[c] * inv_m;
    float var = fmaxf(g_stat[HID + c] * inv_m - mu * mu, 0.f);
    float sc = gamma[c] * rsqrtf(var + EPS);
    g_scale[c] = sc;
    g_shift[c] = beta[c] - mu * sc;
}

__global__ void norm_relu_kernel(int M) {
    int idx = blockIdx.x * blockDim.x + threadIdx.x;
    int total = M * 32;
    if (idx >= total) return;
    int c4 = idx & 31;
    float4 z = ((const float4*)g_z)[idx];
    float4 sc = ((const float4*)g_scale)[c4];
    float4 sh = ((const float4*)g_shift)[c4];
    float4 h;
    h.x = fmaxf(fmaf(z.x, sc.x, sh.x), 0.f);
    h.y = fmaxf(fmaf(z.y, sc.y, sh.y), 0.f);
    h.z = fmaxf(fmaf(z.z, sc.z, sh.z), 0.f);
    h.w = fmaxf(fmaf(z.w, sc.w, sh.w), 0.f);
    ((float4*)g_h)[idx] = h;

    __nv_bfloat16 hx = __float2bfloat16(h.x);
    __nv_bfloat16 hy = __float2bfloat16(h.y);
    __nv_bfloat16 hz = __float2bfloat16(h.z);
    __nv_bfloat16 hw = __float2bfloat16(h.w);
    __nv_bfloat162* phi = (__nv_bfloat162*)&g_ah_hi[(size_t)idx * 4];
    phi[0] = __nv_bfloat162(hx, hy);
    phi[1] = __nv_bfloat162(hz, hw);
    __nv_bfloat162* plo = (__nv_bfloat162*)&g_ah_lo[(size_t)idx * 4];
    plo[0] = __nv_bfloat162(__float2bfloat16(h.x - __bfloat162float(hx)),
                            __float2bfloat16(h.y - __bfloat162float(hy)));
    plo[1] = __nv_bfloat162(__float2bfloat16(h.z - __bfloat162float(hz)),
                            __float2bfloat16(h.w - __bfloat162float(hw)));
}

// ---------------- global mean pool (segmented, batch sorted) ----------------
__global__ void pool_kernel(int G) {
    int g = blockIdx.x;
    int c = threadIdx.x;
    if (g >= G) return;
    int r0 = g_gstart[g];
    int r1 = g_gstart[g + 1];
    float s = 0.f;
    for (int r = r0; r < r1; r++) s += g_h[(size_t)r * HID + c];
    int cnt = r1 - r0;
    g_pooled[(size_t)g * HID + c] = s / (float)(cnt > 1 ? cnt : 1);
}

// ---------------- MLP head ----------------
__global__ void head_kernel(const float* __restrict__ Wh1,
                            const float* __restrict__ bh1,
                            const float* __restrict__ Wh2,
                            const float* __restrict__ bh2,
                            float* __restrict__ out, int G)
{
    int g = blockIdx.x;
    int t = threadIdx.x;
    if (g >= G) return;
    float acc = bh1[t];
    #pragma unroll 8
    for (int k = 0; k < HID; k++)
        acc = fmaf(g_pooled[(size_t)g * HID + k], Wh1[k * HIDH + t], acc);
    float v = fmaxf(acc, 0.f) * Wh2[t];
    #pragma unroll
    for (int off = 16; off; off >>= 1)
        v += __shfl_down_sync(0xffffffff, v, off);
    __shared__ float sred[2];
    if ((t & 31) == 0) sred[t >> 5] = v;
    __syncthreads();
    if (t == 0) out[g] = sred[0] + sred[1] + bh2[0];
}

// ---------------- launch ----------------
extern "C" void kernel_launch(void* const* d_in, const int* in_sizes, int n_in,
                              void* d_out, int out_size) {
    const float* x     = (const float*)d_in[0];
    const void*  ei    = d_in[1];
    const void*  batch = d_in[2];

    const float* W_n0 = (const float*)d_in[3];
    const float* b0   = (const float*)d_in[4];
    const float* W_r0 = (const float*)d_in[5];
    const float* g0   = (const float*)d_in[6];
    const float* be0  = (const float*)d_in[7];

    const float* W_n1 = (const float*)d_in[8];
    const float* b1   = (const float*)d_in[9];
    const float* W_r1 = (const float*)d_in[10];
    const float* g1   = (const float*)d_in[11];
    const float* be1  = (const float*)d_in[12];

    const float* W_n2 = (const float*)d_in[13];
    const float* b2   = (const float*)d_in[14];
    const float* W_r2 = (const float*)d_in[15];
    const float* g2   = (const float*)d_in[16];
    const float* be2  = (const float*)d_in[17];

    const float* Wh1 = (const float*)d_in[18];
    const float* bh1 = (const float*)d_in[19];
    const float* Wh2 = (const float*)d_in[20];
    const float* bh2 = (const float*)d_in[21];

    float* out = (float*)d_out;

    const int N = in_sizes[2];
    const int E = in_sizes[1] / 2;
    const int G = out_size;
    const int IN_CH = in_sizes[0] / N;

    cudaFuncSetAttribute(gemm_mma_kernel, cudaFuncAttributeMaxDynamicSharedMemorySize,
                         SM_TOTAL);

    // ---- index dtype detection + CSR/segment prep ----
    init_flag_kernel<<<1, 1>>>();
    detect_kernel<<<8, 256>>>(ei, in_sizes[1]);
    int nscan = (N + SCAN_B - 1) / SCAN_B;
    zero_indeg_kernel<<<(N + 255) / 256, 256>>>(N);
    count_edges_kernel<<<(E + 255) / 256, 256>>>(ei, E);
    scan1_kernel<<<nscan, SCAN_B>>>(N);
    scan2_kernel<<<1, 32>>>(nscan);
    scan3_kernel<<<(N + 255) / 256, 256>>>(N, E);
    fill_edges_kernel<<<(E + 255) / 256, 256>>>(ei, E);
    gstart_kernel<<<(N + 256) / 256, 256>>>(batch, N, G);

    // ---- bf16 split preprocessing ----
    convert_x_kernel<<<(N * KPAD + 255) / 256, 256>>>(x, N, IN_CH);
    prep_weights_kernel<<<(256 * KPAD + 255) / 256, 256>>>(W_n0, W_r0, 0, IN_CH);
    prep_weights_kernel<<<(256 * KPAD + 255) / 256, 256>>>(W_n1, W_r1, 1, HID);
    prep_weights_kernel<<<(256 * KPAD + 255) / 256, 256>>>(W_n2, W_r2, 2, HID);

    dim3 gemm_grid((N + 127) / 128, 2);
    int agg_blocks  = (N + 7) / 8;
    int norm_blocks = (N * 32 + 255) / 256;

    const float* bb[3] = {b0, b1, b2};
    const float* gg[3] = {g0, g1, g2};
    const float* be[3] = {be0, be1, be2};

    for (int l = 0; l < 3; l++) {
        const uint4* ahi;
        const uint4* alo;
        const uint4* bhi;
        const uint4* blo;
        void* p;
        cudaGetSymbolAddress(&p, (l == 0) ? g_ax_hi : g_ah_hi); ahi = (const uint4*)p;
        cudaGetSymbolAddress(&p, (l == 0) ? g_ax_lo : g_ah_lo); alo = (const uint4*)p;
        cudaGetSymbolAddress(&p, g_bw_hi); bhi = (const uint4*)p + (size_t)l * (256 * KPAD / 8);
        cudaGetSymbolAddress(&p, g_bw_lo); blo = (const uint4*)p + (size_t)l * (256 * KPAD / 8);

        gemm_mma_kernel<<<gemm_grid, 256, SM_TOTAL>>>(ahi, alo, bhi, blo, bb[l], N);
        aggregate_kernel<<<agg_blocks, 256>>>(N);
        zero_stats_kernel<<<1, 256>>>();
        bn_stats_kernel<<<1024, HID>>>(N);
        bn_finalize_kernel<<<1, HID>>>(gg[l], be[l], N);
        norm_relu_kernel<<<norm_blocks, 256>>>(N);
    }

    pool_kernel<<<G, HID>>>(G);
    head_kernel<<<G, HIDH>>>(Wh1, bh1, Wh2, bh2, out, G);
}